// round 7
// baseline (speedup 1.0000x reference)
#include <cuda_runtime.h>
#include <cstdint>
#include <math.h>

// Problem constants
#define BB 8
#define LL 2048
#define DD 1024
#define ZZ 128
#define HH 2048
#define GG 32
#define MP 2048
#define BWL 4224    // Z + H + 2D (logical)
#define BWP 4352    // padded to multiple of 256

// ---------------- scratch (device globals; no cudaMalloc allowed) ----------------
__device__ __align__(16) float g_xn[BB*LL*DD];            //  64 MB
__device__ __align__(16) float g_s1[BB*LL*GG];            //   2 MB
__device__ __align__(16) float g_s2[BB*LL*GG];            //   2 MB
__device__ __align__(16) float g_v [BB*LL*HH];            // 128 MB
__device__ __align__(16) float g_mx[BB*LL*DD];            //  64 MB
__device__ __align__(16) float g_base[(size_t)BB*LL*BWP]; // 285 MB
__device__ __align__(16) float g_S [(size_t)BB*LL*LL];    // 134 MB
__device__ __align__(16) float g_hr[BB*LL*HH];            // 128 MB
__device__ __align__(16) float g_q [BB*LL*ZZ];            //   8 MB
__device__ __align__(16) float g_k [BB*LL*ZZ];            //   8 MB
__device__ __align__(16) float g_Wv[HH*DD];               //   8 MB (tf32-rounded)
__device__ __align__(16) float g_Wh[DD*HH];               //   8 MB (tf32-rounded)
__device__ __align__(16) float g_Wmx[BWP*DD];             //  17.8 MB (rounded+padded)
__device__ __align__(16) float g_bmx[BWP];

__device__ __forceinline__ float siluf(float x){ return x/(1.f+__expf(-x)); }
__device__ __forceinline__ float tf32r(float f){
  uint32_t r; asm("cvt.rna.tf32.f32 %0, %1;" : "=r"(r) : "f"(f));
  return __uint_as_float(r);
}
__device__ __forceinline__ float warpMax(float v){
  #pragma unroll
  for(int o=16;o>0;o>>=1) v=fmaxf(v,__shfl_xor_sync(0xffffffffu,v,o));
  return v;
}
__device__ __forceinline__ float warpSum(float v){
  #pragma unroll
  for(int o=16;o>0;o>>=1) v+=__shfl_xor_sync(0xffffffffu,v,o);
  return v;
}
__device__ __forceinline__ uint32_t smem_u32(const void* p){
  uint32_t a;
  asm("{ .reg .u64 t; cvta.to.shared.u64 t, %1; cvt.u32.u64 %0, t; }" : "=r"(a) : "l"(p));
  return a;
}
__device__ __forceinline__ void cpa16(uint32_t dst, const void* src){
  asm volatile("cp.async.cg.shared.global [%0], [%1], 16;" :: "r"(dst), "l"(src));
}
__device__ __forceinline__ void mma8(float* c, const uint32_t* a, const uint32_t* b){
  asm volatile("mma.sync.aligned.m16n8k8.row.col.f32.tf32.tf32.f32 "
    "{%0,%1,%2,%3}, {%4,%5,%6,%7}, {%8,%9}, {%0,%1,%2,%3};"
    : "+f"(c[0]),"+f"(c[1]),"+f"(c[2]),"+f"(c[3])
    : "r"(a[0]),"r"(a[1]),"r"(a[2]),"r"(a[3]), "r"(b[0]),"r"(b[1]));
}

// ======================= weight prep (round to tf32 / pad) =======================
__global__ void __launch_bounds__(256) wround(const float* __restrict__ in,
                                              float* __restrict__ out, int n){
  int i = blockIdx.x*256 + threadIdx.x;
  if (i < n) out[i] = tf32r(in[i]);
}
__global__ void __launch_bounds__(256) wmx_pad(const float* __restrict__ Wmx,
                                               const float* __restrict__ bmx){
  int i = blockIdx.x*256 + threadIdx.x;     // over BWP*DD
  int r = i >> 10;
  g_Wmx[i] = (r < BWL) ? tf32r(Wmx[i]) : 0.f;
  if (i < BWP) g_bmx[i] = (i < BWL) ? bmx[i] : 0.f;
}

// ======================= timestep_norm: group sums + scan =======================
__global__ void __launch_bounds__(256) tn_scan(const float* __restrict__ x){
  int bg = blockIdx.x; int b = bg >> 5; int g = bg & 31;
  int t = threadIdx.x;
  float c1[8], c2[8];
  float r1 = 0.f, r2 = 0.f;
  const float* xb = x + (size_t)b*LL*DD + g*32;
  #pragma unroll
  for(int i=0;i<8;i++){
    int l = t*8 + i;
    const float4* q = (const float4*)(xb + (size_t)l*DD);
    float a1=0.f, a2=0.f;
    #pragma unroll
    for(int c=0;c<8;c++){
      float4 f = q[c];
      a1 += f.x+f.y+f.z+f.w;
      a2 += f.x*f.x+f.y*f.y+f.z*f.z+f.w*f.w;
    }
    r1 += a1; r2 += a2;
    c1[i] = r1; c2[i] = r2;
  }
  __shared__ float sm1[256], sm2[256];
  sm1[t]=r1; sm2[t]=r2;
  __syncthreads();
  for(int off=1; off<256; off<<=1){
    float a1=0.f, a2=0.f;
    if(t>=off){ a1=sm1[t-off]; a2=sm2[t-off]; }
    __syncthreads();
    sm1[t]+=a1; sm2[t]+=a2;
    __syncthreads();
  }
  float p1 = (t>0)? sm1[t-1] : 0.f;
  float p2 = (t>0)? sm2[t-1] : 0.f;
  #pragma unroll
  for(int i=0;i<8;i++){
    int l = t*8 + i;
    g_s1[((size_t)b*LL + l)*GG + g] = p1 + c1[i];
    g_s2[((size_t)b*LL + l)*GG + g] = p2 + c2[i];
  }
}

__global__ void __launch_bounds__(256) tn_norm_k(
    const float* __restrict__ x, const float* __restrict__ pm,
    const float* __restrict__ plv, const float* __restrict__ w,
    const float* __restrict__ bias){
  int idx = blockIdx.x*256 + threadIdx.x;
  int d  = idx & (DD-1);
  int bl = idx >> 10;
  int l  = bl & (LL-1);
  int g  = d >> 5;
  float s1 = g_s1[(size_t)bl*GG + g];
  float s2 = g_s2[(size_t)bl*GG + g];
  float cnt = 2.0f + 32.0f*(float)(l+1);
  float pmg = pm[g];
  float pv  = expf(plv[g]);
  float mean = (2.0f*pmg + s1)/cnt;
  float var  = (2.0f*(pv + pmg*pmg) + s2)/cnt - mean*mean;
  float xv = x[idx];
  g_xn[idx] = tf32r((xv - mean)*rsqrtf(var + 1e-5f)*w[d] + bias[d]);
}

// ======================= multihead EMA: 16-state linear scan =======================
__global__ void __launch_bounds__(64) ema_k(
    const float* __restrict__ delta, const float* __restrict__ alpha,
    const float* __restrict__ ebeta, const float* __restrict__ egam,
    const float* __restrict__ omega){
  int b = blockIdx.x >> 4;
  int d = ((blockIdx.x & 15) << 6) + threadIdx.x;
  float q[16], pb[16], gs[16], s[16];
  #pragma unroll
  for(int n=0;n<16;n++){
    float p = 1.f/(1.f+expf(-delta[d*16+n]));
    float a = 1.f/(1.f+expf(-alpha[d*16+n]));
    q[n]  = 1.f - p*a;
    pb[n] = p*ebeta[d*16+n];
    gs[n] = egam[d*16+n]*0.25f;
    s[n]  = 0.f;
  }
  float om = omega[d];
  const float* xp = g_xn + (size_t)b*LL*DD + d;
  float*       op = g_mx + (size_t)b*LL*DD + d;
  for(int l=0;l<LL;l++){
    float xv = xp[(size_t)l*DD];
    float o0 = om*xv, o1=0.f, o2=0.f, o3=0.f;
    #pragma unroll
    for(int n=0;n<16;n+=4){
      s[n+0] = q[n+0]*s[n+0] + pb[n+0]*xv; o0 += gs[n+0]*s[n+0];
      s[n+1] = q[n+1]*s[n+1] + pb[n+1]*xv; o1 += gs[n+1]*s[n+1];
      s[n+2] = q[n+2]*s[n+2] + pb[n+2]*xv; o2 += gs[n+2]*s[n+2];
      s[n+3] = q[n+3]*s[n+3] + pb[n+3]*xv; o3 += gs[n+3]*s[n+3];
    }
    op[(size_t)l*DD] = (o0+o1)+(o2+o3);
  }
}

// ======================= RMS norm in place on g_mx (rounded write) =======================
__global__ void __launch_bounds__(256) rms_norm(const float* __restrict__ w){
  int row = blockIdx.x;
  float* p = g_mx + (size_t)row*DD;
  int t = threadIdx.x;
  float v[4]; float ss = 0.f;
  #pragma unroll
  for(int j=0;j<4;j++){ v[j] = p[t + 256*j]; ss += v[j]*v[j]; }
  __shared__ float red[8];
  ss = warpSum(ss);
  if((t&31)==0) red[t>>5] = ss;
  __syncthreads();
  if(t<32){
    float a = (t<8)? red[t] : 0.f;
    a = warpSum(a);
    if(t==0) red[0] = a;
  }
  __syncthreads();
  float sc = rsqrtf(red[0]*(1.0f/DD) + 1e-5f);
  #pragma unroll
  for(int j=0;j<4;j++) p[t+256*j] = tf32r(v[j]*sc*w[t+256*j]);
}

// ======================= q/k materialization (rounded) =======================
__global__ void __launch_bounds__(256) qk_prep(const float* __restrict__ qkg,
                                               const float* __restrict__ qkb){
  int idx = blockIdx.x*256 + threadIdx.x;   // over BB*LL*ZZ
  int bl = idx >> 7, i = idx & 127;
  float zb = g_base[(size_t)bl*BWP + DD + i];
  float s = zb/(1.f+__expf(-zb));
  g_q[idx] = tf32r((s*qkg[i]    + qkb[i])    * 0.0883883476483184f);
  g_k[idx] = tf32r( s*qkg[ZZ+i] + qkb[ZZ+i]);
}

// ======================= row softmax on g_S (rounded write) =======================
__global__ void __launch_bounds__(256) softmax_rows(){
  int row = blockIdx.x;
  float* p = g_S + (size_t)row*LL;
  int t = threadIdx.x;
  float v[8];
  float m = -3.0e38f;
  #pragma unroll
  for(int j=0;j<8;j++){ v[j] = p[t + 256*j]; m = fmaxf(m, v[j]); }
  __shared__ float red[8];
  m = warpMax(m);
  if((t&31)==0) red[t>>5] = m;
  __syncthreads();
  if(t<32){
    float a = (t<8)? red[t] : -3.0e38f;
    a = warpMax(a);
    if(t==0) red[0] = a;
  }
  __syncthreads();
  m = red[0];
  __syncthreads();
  float s = 0.f;
  #pragma unroll
  for(int j=0;j<8;j++){ v[j] = __expf(v[j]-m); s += v[j]; }
  s = warpSum(s);
  if((t&31)==0) red[t>>5] = s;
  __syncthreads();
  if(t<32){
    float a = (t<8)? red[t] : 0.f;
    a = warpSum(a);
    if(t==0) red[0] = a;
  }
  __syncthreads();
  float inv = 1.f/red[0];
  #pragma unroll
  for(int j=0;j<8;j++) p[t + 256*j] = tf32r(v[j]*inv);
}

// ======================= tf32 mma.sync GEMM, BM=128 BN=256 BK=32 =======================
// EPI: 0 = +bias (base), 1 = silu(+bias) (v), 2 = qk (+relbias, causal mask),
//      3 = av (*silu(r)), 4 = final (gated output)
// BLAY: 0 = B is NT [n][k] row-major; 1 = B is NN [k][n] row-major (V)
// 8 warps: 2 (M) x 4 (N); warp tile 64x64; operands pre-rounded to tf32.
#define NST 3
#define SPAD 36
#define A_FL (128*SPAD)          // 4608 floats
#define B_FL 9216                // max(256*36, 32*264)
#define STG_FL (A_FL + B_FL)     // 13824 floats
#define MM_SMEM (NST*STG_FL*4)   // 165888 bytes

template<int EPI, int BLAY>
__global__ void __launch_bounds__(256) mm_mma(
    const float* __restrict__ A, const float* __restrict__ Bw,
    const float* __restrict__ bias, float* __restrict__ C,
    int N, int K, long sAz, long sBz, long sCz, int Mrows,
    const float* __restrict__ xres, const float* __restrict__ relb)
{
  const int tid  = threadIdx.x;
  const int wid  = tid >> 5, lane = tid & 31;
  const int wm   = wid & 1, wn = wid >> 1;       // 2 x 4 warp grid
  const int l4   = lane & 3, l2 = lane >> 2;
  const int bm   = blockIdx.y*128, bn = blockIdx.x*256, z = blockIdx.z;

  if (EPI == 2 && bn >= bm + 128){   // fully masked block: 128 rows x 256 cols
    float4 m4 = make_float4(-1e30f,-1e30f,-1e30f,-1e30f);
    int r = tid >> 1, c0 = (tid & 1) << 7;
    float* cp = C + (size_t)z*sCz + (size_t)(bm + r)*N + bn + c0;
    #pragma unroll
    for(int j=0;j<32;j++) ((float4*)cp)[j] = m4;
    return;
  }

  extern __shared__ float sm[];
  const uint32_t sb = smem_u32(sm);
  int nk = K >> 5;
  if (EPI == 3) nk = (bm + 128) >> 5;   // causal K bound

  const float* Abase = A + (size_t)z*sAz + (size_t)bm*K;
  const float* Bbase = BLAY ? (Bw + (size_t)z*sBz + bn)
                            : (Bw + (size_t)z*sBz + (size_t)bn*K);

  auto load_stage = [&](int s){
    uint32_t st  = sb + (uint32_t)(s % NST)*(STG_FL*4);
    uint32_t stB = st + A_FL*4;
    const float* Ap = Abase + s*32;
    #pragma unroll
    for(int i=0;i<4;i++){
      int idx = tid + (i<<8);
      int row = idx >> 3, cb = (idx & 7) << 2;
      cpa16(st + ((uint32_t)(row*SPAD + cb) << 2), Ap + (size_t)row*K + cb);
    }
    if (BLAY == 0){
      const float* Bp = Bbase + s*32;
      #pragma unroll
      for(int i=0;i<8;i++){
        int idx = tid + (i<<8);
        int row = idx >> 3, cb = (idx & 7) << 2;
        cpa16(stB + ((uint32_t)(row*SPAD + cb) << 2), Bp + (size_t)row*K + cb);
      }
    } else {
      const float* Bp = Bbase + (size_t)(s*32)*N;
      #pragma unroll
      for(int i=0;i<8;i++){
        int idx = tid + (i<<8);
        int row = idx >> 6, cb = (idx & 63) << 2;
        cpa16(stB + ((uint32_t)(row*264 + cb) << 2), Bp + (size_t)row*N + cb);
      }
    }
    asm volatile("cp.async.commit_group;" ::: "memory");
  };

  load_stage(0);
  load_stage(1);

  float c[4][8][4];
  #pragma unroll
  for(int mi=0;mi<4;mi++)
    #pragma unroll
    for(int ni=0;ni<8;ni++)
      #pragma unroll
      for(int r=0;r<4;r++) c[mi][ni][r] = 0.f;

  for(int s=0;s<nk;s++){
    asm volatile("cp.async.wait_group 1;" ::: "memory");
    __syncthreads();
    if (s+2 < nk) load_stage(s+2);
    else asm volatile("cp.async.commit_group;" ::: "memory");
    const float* As_ = sm + (s % NST)*STG_FL;
    const float* Bs_ = As_ + A_FL;
    #pragma unroll
    for(int kk=0;kk<32;kk+=8){
      uint32_t af[4][4], bf[8][2];
      #pragma unroll
      for(int mi=0;mi<4;mi++){
        int r0 = wm*64 + mi*16 + l2;
        af[mi][0] = __float_as_uint(As_[ r0    *SPAD + kk + l4    ]);
        af[mi][1] = __float_as_uint(As_[(r0+8) *SPAD + kk + l4    ]);
        af[mi][2] = __float_as_uint(As_[ r0    *SPAD + kk + l4 + 4]);
        af[mi][3] = __float_as_uint(As_[(r0+8) *SPAD + kk + l4 + 4]);
      }
      #pragma unroll
      for(int ni=0;ni<8;ni++){
        int n0 = wn*64 + ni*8 + l2;
        if (BLAY == 0){
          bf[ni][0] = __float_as_uint(Bs_[n0*SPAD + kk + l4    ]);
          bf[ni][1] = __float_as_uint(Bs_[n0*SPAD + kk + l4 + 4]);
        } else {
          bf[ni][0] = __float_as_uint(Bs_[(kk + l4    )*264 + n0]);
          bf[ni][1] = __float_as_uint(Bs_[(kk + l4 + 4)*264 + n0]);
        }
      }
      #pragma unroll
      for(int mi=0;mi<4;mi++)
        #pragma unroll
        for(int ni=0;ni<8;ni++)
          mma8(c[mi][ni], af[mi], bf[ni]);
    }
    __syncthreads();
  }

  // ---------------- epilogue ----------------
  #pragma unroll
  for(int mi=0;mi<4;mi++){
    #pragma unroll
    for(int h=0;h<2;h++){
      int row  = bm + wm*64 + mi*16 + l2 + h*8;
      int grow = z*Mrows + row;
      float* cp = C + (size_t)z*sCz + (size_t)row*N;
      #pragma unroll
      for(int ni=0;ni<8;ni++){
        int col = bn + wn*64 + ni*8 + 2*l4;
        float v0 = c[mi][ni][2*h+0];
        float v1 = c[mi][ni][2*h+1];
        if (EPI == 0){ v0 += bias[col]; v1 += bias[col+1]; }
        else if (EPI == 1){
          v0 = tf32r(siluf(v0 + bias[col]));
          v1 = tf32r(siluf(v1 + bias[col+1]));
        } else if (EPI == 2){
          v0 += relb[MP-1 + col   - row];
          v1 += relb[MP-1 + col+1 - row];
          if (col   > row) v0 = -1e30f;
          if (col+1 > row) v1 = -1e30f;
        } else if (EPI == 3){
          const float* rr = g_base + (size_t)grow*BWP + (DD+ZZ);
          v0 = tf32r(v0 * siluf(rr[col]));
          v1 = tf32r(v1 * siluf(rr[col+1]));
        } else {
          const float* br = g_base + (size_t)grow*BWP;
          float t0 = siluf(br[DD+ZZ+HH+col]   + v0);
          float t1 = siluf(br[DD+ZZ+HH+col+1] + v1);
          float u0 = 1.f/(1.f+__expf(-br[col]));
          float u1 = 1.f/(1.f+__expf(-br[col+1]));
          float x0 = xres[(size_t)grow*DD + col];
          float x1 = xres[(size_t)grow*DD + col+1];
          v0 = x0 + u0*(t0 - x0);
          v1 = x1 + u1*(t1 - x1);
        }
        *(float2*)(cp + col) = make_float2(v0, v1);
      }
    }
  }
}

// ======================= launch =======================
extern "C" void kernel_launch(void* const* d_in, const int* in_sizes, int n_in,
                              void* d_out, int out_size){
  (void)in_sizes; (void)n_in; (void)out_size;
  const float* x          = (const float*)d_in[0];
  const float* prior_mean = (const float*)d_in[1];
  const float* prior_logv = (const float*)d_in[2];
  const float* tn_weight  = (const float*)d_in[3];
  const float* tn_bias    = (const float*)d_in[4];
  const float* delta      = (const float*)d_in[5];
  const float* alpha      = (const float*)d_in[6];
  const float* ema_beta   = (const float*)d_in[7];
  const float* ema_gamma  = (const float*)d_in[8];
  const float* omega      = (const float*)d_in[9];
  const float* rms_weight = (const float*)d_in[10];
  const float* Wv         = (const float*)d_in[11];
  const float* bv         = (const float*)d_in[12];
  const float* Wmx        = (const float*)d_in[13];
  const float* bmx        = (const float*)d_in[14];
  const float* Wh         = (const float*)d_in[15];
  const float* qk_gamma   = (const float*)d_in[16];
  const float* qk_beta    = (const float*)d_in[17];
  const float* rel_bias   = (const float*)d_in[18];
  float* out = (float*)d_out;

  float *p_xn, *p_mx, *p_v, *p_base, *p_S, *p_hr, *p_q, *p_k;
  float *p_Wv, *p_Wh, *p_Wmx, *p_bmx;
  cudaGetSymbolAddress((void**)&p_xn,   g_xn);
  cudaGetSymbolAddress((void**)&p_mx,   g_mx);
  cudaGetSymbolAddress((void**)&p_v,    g_v);
  cudaGetSymbolAddress((void**)&p_base, g_base);
  cudaGetSymbolAddress((void**)&p_S,    g_S);
  cudaGetSymbolAddress((void**)&p_hr,   g_hr);
  cudaGetSymbolAddress((void**)&p_q,    g_q);
  cudaGetSymbolAddress((void**)&p_k,    g_k);
  cudaGetSymbolAddress((void**)&p_Wv,   g_Wv);
  cudaGetSymbolAddress((void**)&p_Wh,   g_Wh);
  cudaGetSymbolAddress((void**)&p_Wmx,  g_Wmx);
  cudaGetSymbolAddress((void**)&p_bmx,  g_bmx);

  cudaFuncSetAttribute(mm_mma<0,0>, cudaFuncAttributeMaxDynamicSharedMemorySize, MM_SMEM);
  cudaFuncSetAttribute(mm_mma<1,0>, cudaFuncAttributeMaxDynamicSharedMemorySize, MM_SMEM);
  cudaFuncSetAttribute(mm_mma<2,0>, cudaFuncAttributeMaxDynamicSharedMemorySize, MM_SMEM);
  cudaFuncSetAttribute(mm_mma<3,1>, cudaFuncAttributeMaxDynamicSharedMemorySize, MM_SMEM);
  cudaFuncSetAttribute(mm_mma<4,0>, cudaFuncAttributeMaxDynamicSharedMemorySize, MM_SMEM);

  // 0) weight prep (round to tf32, pad Wmx)
  wround<<<(HH*DD)/256, 256>>>(Wv, p_Wv, HH*DD);
  wround<<<(DD*HH)/256, 256>>>(Wh, p_Wh, DD*HH);
  wmx_pad<<<(BWP*DD)/256, 256>>>(Wmx, bmx);

  // 1) timestep norm
  tn_scan<<<BB*GG, 256>>>(x);
  tn_norm_k<<<(BB*LL*DD)/256, 256>>>(x, prior_mean, prior_logv, tn_weight, tn_bias);
  // 2) v = silu(xn @ Wv^T + bv)
  mm_mma<1,0><<<dim3(HH/256, (BB*LL)/128, 1), 256, MM_SMEM>>>(
      p_xn, p_Wv, bv, p_v, HH, DD, 0,0,0, BB*LL, nullptr, nullptr);
  // 3) EMA scan + omega residual -> g_mx
  ema_k<<<BB*16, 64>>>(delta, alpha, ema_beta, ema_gamma, omega);
  // 4) rmsnorm in place
  rms_norm<<<BB*LL, 256>>>(rms_weight);
  // 5) base = mx @ Wmx^T + bmx  (N padded to 4352)
  mm_mma<0,0><<<dim3(BWP/256, (BB*LL)/128, 1), 256, MM_SMEM>>>(
      p_mx, p_Wmx, p_bmx, p_base, BWP, DD, 0,0,0, BB*LL, nullptr, nullptr);
  // 6) q/k materialization
  qk_prep<<<(BB*LL*ZZ)/256, 256>>>(qk_gamma, qk_beta);
  // 7) S = q@k^T + rel_bias, causal
  mm_mma<2,0><<<dim3(LL/256, LL/128, BB), 256, MM_SMEM>>>(
      p_q, p_k, nullptr, p_S, LL, ZZ, (long)LL*ZZ, (long)LL*ZZ, (long)LL*LL, LL,
      nullptr, rel_bias);
  // 8) softmax
  softmax_rows<<<BB*LL, 256>>>();
  // 9) hr = (attn @ v) * silu(r)   [causal-bounded K; V in NN layout]
  mm_mma<3,1><<<dim3(HH/256, LL/128, BB), 256, MM_SMEM>>>(
      p_S, p_v, nullptr, p_hr, HH, LL, (long)LL*LL, (long)LL*HH, (long)LL*HH, LL,
      nullptr, nullptr);
  // 10) out = x + u*(silu(hx + hr@Wh^T) - x)
  mm_mma<4,0><<<dim3(DD/256, (BB*LL)/128, 1), 256, MM_SMEM>>>(
      p_hr, p_Wh, nullptr, out, DD, HH, 0,0,0, BB*LL, x, nullptr);
}

// round 8
// speedup vs baseline: 1.1551x; 1.1551x over previous
#include <cuda_runtime.h>
#include <cstdint>
#include <math.h>

// Problem constants
#define BB 8
#define LL 2048
#define DD 1024
#define ZZ 128
#define HH 2048
#define GG 32
#define MP 2048
#define BW 4224    // Z + H + 2D  (= 33 * 128, no padding needed)

// ---------------- scratch (device globals; no cudaMalloc allowed) ----------------
__device__ __align__(16) float g_xn[BB*LL*DD];            //  64 MB
__device__ __align__(16) float g_s1[BB*LL*GG];            //   2 MB
__device__ __align__(16) float g_s2[BB*LL*GG];            //   2 MB
__device__ __align__(16) float g_v [BB*LL*HH];            // 128 MB
__device__ __align__(16) float g_mx[BB*LL*DD];            //  64 MB
__device__ __align__(16) float g_base[(size_t)BB*LL*BW];  // 277 MB
__device__ __align__(16) float g_S [(size_t)BB*LL*LL];    // 134 MB
__device__ __align__(16) float g_hr[BB*LL*HH];            // 128 MB
__device__ __align__(16) float g_q [BB*LL*ZZ];            //   8 MB
__device__ __align__(16) float g_k [BB*LL*ZZ];            //   8 MB
__device__ __align__(16) float g_Wv[HH*DD];               //   8 MB (tf32-rounded)
__device__ __align__(16) float g_Wh[DD*HH];               //   8 MB (tf32-rounded)
__device__ __align__(16) float g_Wmx[BW*DD];              //  17.3 MB (tf32-rounded)

__device__ __forceinline__ float siluf(float x){ return x/(1.f+__expf(-x)); }
__device__ __forceinline__ float tf32r(float f){
  uint32_t r; asm("cvt.rna.tf32.f32 %0, %1;" : "=r"(r) : "f"(f));
  return __uint_as_float(r);
}
__device__ __forceinline__ float warpMax(float v){
  #pragma unroll
  for(int o=16;o>0;o>>=1) v=fmaxf(v,__shfl_xor_sync(0xffffffffu,v,o));
  return v;
}
__device__ __forceinline__ float warpSum(float v){
  #pragma unroll
  for(int o=16;o>0;o>>=1) v+=__shfl_xor_sync(0xffffffffu,v,o);
  return v;
}
__device__ __forceinline__ uint32_t smem_u32(const void* p){
  uint32_t a;
  asm("{ .reg .u64 t; cvta.to.shared.u64 t, %1; cvt.u32.u64 %0, t; }" : "=r"(a) : "l"(p));
  return a;
}
__device__ __forceinline__ void cpa16(uint32_t dst, const void* src){
  asm volatile("cp.async.cg.shared.global [%0], [%1], 16;" :: "r"(dst), "l"(src));
}
__device__ __forceinline__ void mma8(float* c, const uint32_t* a, const uint32_t* b){
  asm volatile("mma.sync.aligned.m16n8k8.row.col.f32.tf32.tf32.f32 "
    "{%0,%1,%2,%3}, {%4,%5,%6,%7}, {%8,%9}, {%0,%1,%2,%3};"
    : "+f"(c[0]),"+f"(c[1]),"+f"(c[2]),"+f"(c[3])
    : "r"(a[0]),"r"(a[1]),"r"(a[2]),"r"(a[3]), "r"(b[0]),"r"(b[1]));
}

// ======================= weight prep (round to tf32) =======================
__global__ void __launch_bounds__(256) wround(const float* __restrict__ in,
                                              float* __restrict__ out, int n){
  int i = blockIdx.x*256 + threadIdx.x;
  if (i < n) out[i] = tf32r(in[i]);
}

// ======================= timestep_norm: group sums + scan =======================
__global__ void __launch_bounds__(256) tn_scan(const float* __restrict__ x){
  int bg = blockIdx.x; int b = bg >> 5; int g = bg & 31;
  int t = threadIdx.x;
  float c1[8], c2[8];
  float r1 = 0.f, r2 = 0.f;
  const float* xb = x + (size_t)b*LL*DD + g*32;
  #pragma unroll
  for(int i=0;i<8;i++){
    int l = t*8 + i;
    const float4* q = (const float4*)(xb + (size_t)l*DD);
    float a1=0.f, a2=0.f;
    #pragma unroll
    for(int c=0;c<8;c++){
      float4 f = q[c];
      a1 += f.x+f.y+f.z+f.w;
      a2 += f.x*f.x+f.y*f.y+f.z*f.z+f.w*f.w;
    }
    r1 += a1; r2 += a2;
    c1[i] = r1; c2[i] = r2;
  }
  __shared__ float sm1[256], sm2[256];
  sm1[t]=r1; sm2[t]=r2;
  __syncthreads();
  for(int off=1; off<256; off<<=1){
    float a1=0.f, a2=0.f;
    if(t>=off){ a1=sm1[t-off]; a2=sm2[t-off]; }
    __syncthreads();
    sm1[t]+=a1; sm2[t]+=a2;
    __syncthreads();
  }
  float p1 = (t>0)? sm1[t-1] : 0.f;
  float p2 = (t>0)? sm2[t-1] : 0.f;
  #pragma unroll
  for(int i=0;i<8;i++){
    int l = t*8 + i;
    g_s1[((size_t)b*LL + l)*GG + g] = p1 + c1[i];
    g_s2[((size_t)b*LL + l)*GG + g] = p2 + c2[i];
  }
}

__global__ void __launch_bounds__(256) tn_norm_k(
    const float* __restrict__ x, const float* __restrict__ pm,
    const float* __restrict__ plv, const float* __restrict__ w,
    const float* __restrict__ bias){
  int idx = blockIdx.x*256 + threadIdx.x;
  int d  = idx & (DD-1);
  int bl = idx >> 10;
  int l  = bl & (LL-1);
  int g  = d >> 5;
  float s1 = g_s1[(size_t)bl*GG + g];
  float s2 = g_s2[(size_t)bl*GG + g];
  float cnt = 2.0f + 32.0f*(float)(l+1);
  float pmg = pm[g];
  float pv  = expf(plv[g]);
  float mean = (2.0f*pmg + s1)/cnt;
  float var  = (2.0f*(pv + pmg*pmg) + s2)/cnt - mean*mean;
  float xv = x[idx];
  g_xn[idx] = tf32r((xv - mean)*rsqrtf(var + 1e-5f)*w[d] + bias[d]);
}

// ======================= multihead EMA: 16-state linear scan =======================
__global__ void __launch_bounds__(64) ema_k(
    const float* __restrict__ delta, const float* __restrict__ alpha,
    const float* __restrict__ ebeta, const float* __restrict__ egam,
    const float* __restrict__ omega){
  int b = blockIdx.x >> 4;
  int d = ((blockIdx.x & 15) << 6) + threadIdx.x;
  float q[16], pb[16], gs[16], s[16];
  #pragma unroll
  for(int n=0;n<16;n++){
    float p = 1.f/(1.f+expf(-delta[d*16+n]));
    float a = 1.f/(1.f+expf(-alpha[d*16+n]));
    q[n]  = 1.f - p*a;
    pb[n] = p*ebeta[d*16+n];
    gs[n] = egam[d*16+n]*0.25f;
    s[n]  = 0.f;
  }
  float om = omega[d];
  const float* xp = g_xn + (size_t)b*LL*DD + d;
  float*       op = g_mx + (size_t)b*LL*DD + d;
  for(int l=0;l<LL;l++){
    float xv = xp[(size_t)l*DD];
    float o0 = om*xv, o1=0.f, o2=0.f, o3=0.f;
    #pragma unroll
    for(int n=0;n<16;n+=4){
      s[n+0] = q[n+0]*s[n+0] + pb[n+0]*xv; o0 += gs[n+0]*s[n+0];
      s[n+1] = q[n+1]*s[n+1] + pb[n+1]*xv; o1 += gs[n+1]*s[n+1];
      s[n+2] = q[n+2]*s[n+2] + pb[n+2]*xv; o2 += gs[n+2]*s[n+2];
      s[n+3] = q[n+3]*s[n+3] + pb[n+3]*xv; o3 += gs[n+3]*s[n+3];
    }
    op[(size_t)l*DD] = (o0+o1)+(o2+o3);
  }
}

// ======================= RMS norm in place on g_mx (rounded write) =======================
__global__ void __launch_bounds__(256) rms_norm(const float* __restrict__ w){
  int row = blockIdx.x;
  float* p = g_mx + (size_t)row*DD;
  int t = threadIdx.x;
  float v[4]; float ss = 0.f;
  #pragma unroll
  for(int j=0;j<4;j++){ v[j] = p[t + 256*j]; ss += v[j]*v[j]; }
  __shared__ float red[8];
  ss = warpSum(ss);
  if((t&31)==0) red[t>>5] = ss;
  __syncthreads();
  if(t<32){
    float a = (t<8)? red[t] : 0.f;
    a = warpSum(a);
    if(t==0) red[0] = a;
  }
  __syncthreads();
  float sc = rsqrtf(red[0]*(1.0f/DD) + 1e-5f);
  #pragma unroll
  for(int j=0;j<4;j++) p[t+256*j] = tf32r(v[j]*sc*w[t+256*j]);
}

// ======================= q/k materialization (rounded) =======================
__global__ void __launch_bounds__(256) qk_prep(const float* __restrict__ qkg,
                                               const float* __restrict__ qkb){
  int idx = blockIdx.x*256 + threadIdx.x;   // over BB*LL*ZZ
  int bl = idx >> 7, i = idx & 127;
  float zb = g_base[(size_t)bl*BW + DD + i];
  float s = zb/(1.f+__expf(-zb));
  g_q[idx] = tf32r((s*qkg[i]    + qkb[i])    * 0.0883883476483184f);
  g_k[idx] = tf32r( s*qkg[ZZ+i] + qkb[ZZ+i]);
}

// ======================= row softmax on g_S (causal-bounded) =======================
__global__ void __launch_bounds__(256) softmax_rows(){
  int row = blockIdx.x;              // b*L + l
  int l   = row & (LL-1);
  int ncols = ((l >> 7) + 1) << 7;   // only cols < diag-block end are live
  float* p = g_S + (size_t)row*LL;
  int t = threadIdx.x;
  float v[8];
  float m = -3.0e38f;
  #pragma unroll
  for(int j=0;j<8;j++){
    int col = t + 256*j;
    v[j] = (col < ncols) ? p[col] : -3.0e38f;
    m = fmaxf(m, v[j]);
  }
  __shared__ float red[8];
  m = warpMax(m);
  if((t&31)==0) red[t>>5] = m;
  __syncthreads();
  if(t<32){
    float a = (t<8)? red[t] : -3.0e38f;
    a = warpMax(a);
    if(t==0) red[0] = a;
  }
  __syncthreads();
  m = red[0];
  __syncthreads();
  float s = 0.f;
  #pragma unroll
  for(int j=0;j<8;j++){ v[j] = __expf(v[j]-m); s += v[j]; }
  s = warpSum(s);
  if((t&31)==0) red[t>>5] = s;
  __syncthreads();
  if(t<32){
    float a = (t<8)? red[t] : 0.f;
    a = warpSum(a);
    if(t==0) red[0] = a;
  }
  __syncthreads();
  float inv = 1.f/red[0];
  #pragma unroll
  for(int j=0;j<8;j++){
    int col = t + 256*j;
    if (col < ncols) p[col] = tf32r(v[j]*inv);
  }
}

// ======================= tf32 mma.sync GEMM, BM=BN=128 BK=32, 2 CTAs/SM =======================
// EPI: 0 = +bias (base), 1 = silu(+bias) (v), 2 = qk (+relbias, causal mask),
//      3 = av (*silu(r)), 4 = final (gated output)
// BLAY: 0 = B is NT [n][k] row-major; 1 = B is NN [k][n] row-major (V)
// 8 warps: 2 (M) x 4 (N); warp tile 64x32; operands pre-rounded to tf32.
#define NST 3
#define SPAD 36
#define BPADN 136                 // NN B row stride (floats): banks 8*l4+l2 distinct
#define A_FL (128*SPAD)           // 4608 floats
#define B_FL (128*SPAD)           // 4608 floats (NT); NN uses 32*136=4352 of it
#define STG_FL (A_FL + B_FL)      // 9216 floats
#define MM_SMEM (NST*STG_FL*4)    // 110592 bytes -> 2 CTAs/SM

template<int EPI, int BLAY>
__global__ void __launch_bounds__(256,2) mm_mma(
    const float* __restrict__ A, const float* __restrict__ Bw,
    const float* __restrict__ bias, float* __restrict__ C,
    int N, int K, long sAz, long sBz, long sCz, int Mrows,
    const float* __restrict__ xres, const float* __restrict__ relb)
{
  const int tid  = threadIdx.x;
  const int wid  = tid >> 5, lane = tid & 31;
  const int wm   = wid & 1, wn = wid >> 1;       // 2 x 4 warp grid
  const int l4   = lane & 3, l2 = lane >> 2;
  const int bm   = blockIdx.y*128, bn = blockIdx.x*128, z = blockIdx.z;

  if (EPI == 2 && bn > bm) return;   // fully-masked qk block: never read downstream

  extern __shared__ float sm[];
  const uint32_t sb = smem_u32(sm);
  int nk = K >> 5;
  if (EPI == 3) nk = (bm + 128) >> 5;   // causal K bound

  const float* Abase = A + (size_t)z*sAz + (size_t)bm*K;
  const float* Bbase = BLAY ? (Bw + (size_t)z*sBz + bn)
                            : (Bw + (size_t)z*sBz + (size_t)bn*K);

  auto load_stage = [&](int s){
    uint32_t st  = sb + (uint32_t)(s % NST)*(STG_FL*4);
    uint32_t stB = st + A_FL*4;
    const float* Ap = Abase + s*32;
    #pragma unroll
    for(int i=0;i<4;i++){
      int idx = tid + (i<<8);
      int row = idx >> 3, cb = (idx & 7) << 2;
      cpa16(st + ((uint32_t)(row*SPAD + cb) << 2), Ap + (size_t)row*K + cb);
    }
    if (BLAY == 0){
      const float* Bp = Bbase + s*32;
      #pragma unroll
      for(int i=0;i<4;i++){
        int idx = tid + (i<<8);
        int row = idx >> 3, cb = (idx & 7) << 2;
        cpa16(stB + ((uint32_t)(row*SPAD + cb) << 2), Bp + (size_t)row*K + cb);
      }
    } else {
      const float* Bp = Bbase + (size_t)(s*32)*N;
      #pragma unroll
      for(int i=0;i<4;i++){
        int idx = tid + (i<<8);
        int row = idx >> 5, cb = (idx & 31) << 2;
        cpa16(stB + ((uint32_t)(row*BPADN + cb) << 2), Bp + (size_t)row*N + cb);
      }
    }
    asm volatile("cp.async.commit_group;" ::: "memory");
  };

  load_stage(0);
  load_stage(1);

  float c[4][4][4];
  #pragma unroll
  for(int mi=0;mi<4;mi++)
    #pragma unroll
    for(int ni=0;ni<4;ni++)
      #pragma unroll
      for(int r=0;r<4;r++) c[mi][ni][r] = 0.f;

  for(int s=0;s<nk;s++){
    asm volatile("cp.async.wait_group 1;" ::: "memory");
    __syncthreads();
    if (s+2 < nk) load_stage(s+2);
    else asm volatile("cp.async.commit_group;" ::: "memory");
    const float* As_ = sm + (s % NST)*STG_FL;
    const float* Bs_ = As_ + A_FL;
    #pragma unroll
    for(int kk=0;kk<32;kk+=8){
      uint32_t af[4][4], bf[4][2];
      #pragma unroll
      for(int mi=0;mi<4;mi++){
        int r0 = wm*64 + mi*16 + l2;
        af[mi][0] = __float_as_uint(As_[ r0    *SPAD + kk + l4    ]);
        af[mi][1] = __float_as_uint(As_[(r0+8) *SPAD + kk + l4    ]);
        af[mi][2] = __float_as_uint(As_[ r0    *SPAD + kk + l4 + 4]);
        af[mi][3] = __float_as_uint(As_[(r0+8) *SPAD + kk + l4 + 4]);
      }
      #pragma unroll
      for(int ni=0;ni<4;ni++){
        int n0 = wn*32 + ni*8 + l2;
        if (BLAY == 0){
          bf[ni][0] = __float_as_uint(Bs_[n0*SPAD + kk + l4    ]);
          bf[ni][1] = __float_as_uint(Bs_[n0*SPAD + kk + l4 + 4]);
        } else {
          bf[ni][0] = __float_as_uint(Bs_[(kk + l4    )*BPADN + n0]);
          bf[ni][1] = __float_as_uint(Bs_[(kk + l4 + 4)*BPADN + n0]);
        }
      }
      #pragma unroll
      for(int mi=0;mi<4;mi++)
        #pragma unroll
        for(int ni=0;ni<4;ni++)
          mma8(c[mi][ni], af[mi], bf[ni]);
    }
    __syncthreads();
  }

  // ---------------- epilogue ----------------
  #pragma unroll
  for(int mi=0;mi<4;mi++){
    #pragma unroll
    for(int h=0;h<2;h++){
      int row  = bm + wm*64 + mi*16 + l2 + h*8;
      int grow = z*Mrows + row;
      float* cp = C + (size_t)z*sCz + (size_t)row*N;
      #pragma unroll
      for(int ni=0;ni<4;ni++){
        int col = bn + wn*32 + ni*8 + 2*l4;
        float v0 = c[mi][ni][2*h+0];
        float v1 = c[mi][ni][2*h+1];
        if (EPI == 0){ v0 += bias[col]; v1 += bias[col+1]; }
        else if (EPI == 1){
          v0 = tf32r(siluf(v0 + bias[col]));
          v1 = tf32r(siluf(v1 + bias[col+1]));
        } else if (EPI == 2){
          v0 += relb[MP-1 + col   - row];
          v1 += relb[MP-1 + col+1 - row];
          if (col   > row) v0 = -1e30f;
          if (col+1 > row) v1 = -1e30f;
        } else if (EPI == 3){
          const float* rr = g_base + (size_t)grow*BW + (DD+ZZ);
          v0 = tf32r(v0 * siluf(rr[col]));
          v1 = tf32r(v1 * siluf(rr[col+1]));
        } else {
          const float* br = g_base + (size_t)grow*BW;
          float t0 = siluf(br[DD+ZZ+HH+col]   + v0);
          float t1 = siluf(br[DD+ZZ+HH+col+1] + v1);
          float u0 = 1.f/(1.f+__expf(-br[col]));
          float u1 = 1.f/(1.f+__expf(-br[col+1]));
          float x0 = xres[(size_t)grow*DD + col];
          float x1 = xres[(size_t)grow*DD + col+1];
          v0 = x0 + u0*(t0 - x0);
          v1 = x1 + u1*(t1 - x1);
        }
        *(float2*)(cp + col) = make_float2(v0, v1);
      }
    }
  }
}

// ======================= launch =======================
extern "C" void kernel_launch(void* const* d_in, const int* in_sizes, int n_in,
                              void* d_out, int out_size){
  (void)in_sizes; (void)n_in; (void)out_size;
  const float* x          = (const float*)d_in[0];
  const float* prior_mean = (const float*)d_in[1];
  const float* prior_logv = (const float*)d_in[2];
  const float* tn_weight  = (const float*)d_in[3];
  const float* tn_bias    = (const float*)d_in[4];
  const float* delta      = (const float*)d_in[5];
  const float* alpha      = (const float*)d_in[6];
  const float* ema_beta   = (const float*)d_in[7];
  const float* ema_gamma  = (const float*)d_in[8];
  const float* omega      = (const float*)d_in[9];
  const float* rms_weight = (const float*)d_in[10];
  const float* Wv         = (const float*)d_in[11];
  const float* bv         = (const float*)d_in[12];
  const float* Wmx        = (const float*)d_in[13];
  const float* bmx        = (const float*)d_in[14];
  const float* Wh         = (const float*)d_in[15];
  const float* qk_gamma   = (const float*)d_in[16];
  const float* qk_beta    = (const float*)d_in[17];
  const float* rel_bias   = (const float*)d_in[18];
  float* out = (float*)d_out;

  float *p_xn, *p_mx, *p_v, *p_base, *p_S, *p_hr, *p_q, *p_k;
  float *p_Wv, *p_Wh, *p_Wmx;
  cudaGetSymbolAddress((void**)&p_xn,   g_xn);
  cudaGetSymbolAddress((void**)&p_mx,   g_mx);
  cudaGetSymbolAddress((void**)&p_v,    g_v);
  cudaGetSymbolAddress((void**)&p_base, g_base);
  cudaGetSymbolAddress((void**)&p_S,    g_S);
  cudaGetSymbolAddress((void**)&p_hr,   g_hr);
  cudaGetSymbolAddress((void**)&p_q,    g_q);
  cudaGetSymbolAddress((void**)&p_k,    g_k);
  cudaGetSymbolAddress((void**)&p_Wv,   g_Wv);
  cudaGetSymbolAddress((void**)&p_Wh,   g_Wh);
  cudaGetSymbolAddress((void**)&p_Wmx,  g_Wmx);

  cudaFuncSetAttribute(mm_mma<0,0>, cudaFuncAttributeMaxDynamicSharedMemorySize, MM_SMEM);
  cudaFuncSetAttribute(mm_mma<1,0>, cudaFuncAttributeMaxDynamicSharedMemorySize, MM_SMEM);
  cudaFuncSetAttribute(mm_mma<2,0>, cudaFuncAttributeMaxDynamicSharedMemorySize, MM_SMEM);
  cudaFuncSetAttribute(mm_mma<3,1>, cudaFuncAttributeMaxDynamicSharedMemorySize, MM_SMEM);
  cudaFuncSetAttribute(mm_mma<4,0>, cudaFuncAttributeMaxDynamicSharedMemorySize, MM_SMEM);

  // 0) weight prep (round to tf32)
  wround<<<(HH*DD)/256, 256>>>(Wv, p_Wv, HH*DD);
  wround<<<(DD*HH)/256, 256>>>(Wh, p_Wh, DD*HH);
  wround<<<(BW*DD)/256, 256>>>(Wmx, p_Wmx, BW*DD);

  // 1) timestep norm
  tn_scan<<<BB*GG, 256>>>(x);
  tn_norm_k<<<(BB*LL*DD)/256, 256>>>(x, prior_mean, prior_logv, tn_weight, tn_bias);
  // 2) v = silu(xn @ Wv^T + bv)
  mm_mma<1,0><<<dim3(HH/128, (BB*LL)/128, 1), 256, MM_SMEM>>>(
      p_xn, p_Wv, bv, p_v, HH, DD, 0,0,0, BB*LL, nullptr, nullptr);
  // 3) EMA scan + omega residual -> g_mx
  ema_k<<<BB*16, 64>>>(delta, alpha, ema_beta, ema_gamma, omega);
  // 4) rmsnorm in place
  rms_norm<<<BB*LL, 256>>>(rms_weight);
  // 5) base = mx @ Wmx^T + bmx
  mm_mma<0,0><<<dim3(BW/128, (BB*LL)/128, 1), 256, MM_SMEM>>>(
      p_mx, p_Wmx, bmx, p_base, BW, DD, 0,0,0, BB*LL, nullptr, nullptr);
  // 6) q/k materialization
  qk_prep<<<(BB*LL*ZZ)/256, 256>>>(qk_gamma, qk_beta);
  // 7) S = q@k^T + rel_bias, causal (masked blocks skipped)
  mm_mma<2,0><<<dim3(LL/128, LL/128, BB), 256, MM_SMEM>>>(
      p_q, p_k, nullptr, p_S, LL, ZZ, (long)LL*ZZ, (long)LL*ZZ, (long)LL*LL, LL,
      nullptr, rel_bias);
  // 8) softmax (causal-bounded)
  softmax_rows<<<BB*LL, 256>>>();
  // 9) hr = (attn @ v) * silu(r)   [causal-bounded K; V in NN layout]
  mm_mma<3,1><<<dim3(HH/128, LL/128, BB), 256, MM_SMEM>>>(
      p_S, p_v, nullptr, p_hr, HH, LL, (long)LL*LL, (long)LL*HH, (long)LL*HH, LL,
      nullptr, nullptr);
  // 10) out = x + u*(silu(hx + hr@Wh^T) - x)
  mm_mma<4,0><<<dim3(DD/128, (BB*LL)/128, 1), 256, MM_SMEM>>>(
      p_hr, p_Wh, nullptr, out, DD, HH, 0,0,0, BB*LL, x, nullptr);
}